// round 4
// baseline (speedup 1.0000x reference)
#include <cuda_runtime.h>
#include <cuda_bf16.h>

// Dilate (zero-insertion upsample) with stride (2,2):
//   in : (16, 64, 256, 256) fp32
//   out: (16, 64, 512, 512) fp32, out[b,c,2i,2j] = in[b,c,i,j], rest 0.
//
// R1 layout (one output float4 per thread, warp-contiguous stores) +
// ILP x2 (each warp owns 64 consecutive float4 of one output row; lane
// handles offsets lane and lane+32) + streaming cache hints.
// Traffic: 268MB read + 1.074GB write = the exact floor.

#ifndef DIL_THREADS
#define DIL_THREADS 256
#endif

__global__ void __launch_bounds__(DIL_THREADS)
Dilate_35708358099161_kernel(const float2* __restrict__ in2,
                             float4* __restrict__ out4)
{
    unsigned int tid  = blockIdx.x * DIL_THREADS + threadIdx.x;
    unsigned int warp = tid >> 5;
    unsigned int lane = tid & 31u;

    // each warp owns 64 consecutive float4 (1KB) within one output row
    unsigned int v0 = (warp << 6) + lane;   // lane's first float4
    unsigned int v1 = v0 + 32u;             // lane's second float4

    // 128 float4 per out row; a 64-aligned chunk never crosses a row
    unsigned int row = v0 >> 7;             // global out-row index
    unsigned int h   = row & 511u;          // out row within image

    const float4 z = make_float4(0.f, 0.f, 0.f, 0.f);

    if (h & 1u) {
        __stcs(&out4[v0], z);
        __stcs(&out4[v1], z);
    } else {
        unsigned int bc   = row >> 9;       // image index, 0..1023
        unsigned int hin  = h >> 1;         // input row, 0..255
        unsigned int base = (bc << 15) + (hin << 7);  // float2 units

        // two independent 8B loads, each warp-coalesced (256B)
        float2 a = __ldcs(&in2[base + (v0 & 127u)]);
        float2 b = __ldcs(&in2[base + (v1 & 127u)]);

        __stcs(&out4[v0], make_float4(a.x, 0.f, a.y, 0.f));
        __stcs(&out4[v1], make_float4(b.x, 0.f, b.y, 0.f));
    }
}

extern "C" void kernel_launch(void* const* d_in, const int* in_sizes, int n_in,
                              void* d_out, int out_size)
{
    const float2* in2 = (const float2*)d_in[0];
    float4* out4 = (float4*)d_out;

    // out_size = 268,435,456 floats -> 67,108,864 float4 -> /2 per thread
    const unsigned int nthreads = (unsigned int)(out_size / 8);
    const unsigned int blocks = nthreads / DIL_THREADS;  // exact: 131,072

    Dilate_35708358099161_kernel<<<blocks, DIL_THREADS>>>(in2, out4);
}

// round 5
// speedup vs baseline: 1.0088x; 1.0088x over previous
#include <cuda_runtime.h>
#include <cuda_bf16.h>

// Dilate (zero-insertion upsample) with stride (2,2):
//   in : (16, 64, 256, 256) fp32
//   out: (16, 64, 512, 512) fp32, out[b,c,2i,2j] = in[b,c,i,j], rest 0.
//
// One output row (2KB = 128 float4) per WARP. Lane handles float4 offsets
// lane + {0,32,64,96} -> four warp-contiguous 512B stores covering the row.
// Row parity is warp-uniform -> zero divergence. Even rows front-batch four
// 256B-coalesced input loads (MLP=4) before the four stores.
// Traffic: 268MB read + 1.074GB write = the exact floor.

#ifndef DIL_THREADS
#define DIL_THREADS 256
#endif

__global__ void __launch_bounds__(DIL_THREADS)
Dilate_35708358099161_kernel(const float2* __restrict__ in2,
                             float4* __restrict__ out4)
{
    unsigned int tid  = blockIdx.x * DIL_THREADS + threadIdx.x;
    unsigned int row  = tid >> 5;        // global output row, one per warp
    unsigned int lane = tid & 31u;

    unsigned int h = row & 511u;         // out row within image
    unsigned int v = (row << 7) + lane;  // first float4 index for this lane

    const float4 z = make_float4(0.f, 0.f, 0.f, 0.f);

    if (h & 1u) {
        __stcs(&out4[v],       z);
        __stcs(&out4[v + 32],  z);
        __stcs(&out4[v + 64],  z);
        __stcs(&out4[v + 96],  z);
    } else {
        unsigned int bc   = row >> 9;    // image index, 0..1023
        unsigned int hin  = h >> 1;      // input row, 0..255
        unsigned int base = (bc << 15) + (hin << 7) + lane;  // float2 units

        // four independent 256B-coalesced loads (full 1KB input row per warp)
        float2 a = __ldcs(&in2[base]);
        float2 b = __ldcs(&in2[base + 32]);
        float2 c = __ldcs(&in2[base + 64]);
        float2 d = __ldcs(&in2[base + 96]);

        __stcs(&out4[v],      make_float4(a.x, 0.f, a.y, 0.f));
        __stcs(&out4[v + 32], make_float4(b.x, 0.f, b.y, 0.f));
        __stcs(&out4[v + 64], make_float4(c.x, 0.f, c.y, 0.f));
        __stcs(&out4[v + 96], make_float4(d.x, 0.f, d.y, 0.f));
    }
}

extern "C" void kernel_launch(void* const* d_in, const int* in_sizes, int n_in,
                              void* d_out, int out_size)
{
    const float2* in2 = (const float2*)d_in[0];
    float4* out4 = (float4*)d_out;

    // out rows = out_size / 512 = 524,288; one warp per row
    const unsigned int nthreads = (unsigned int)(out_size / 16);
    const unsigned int blocks = nthreads / DIL_THREADS;  // exact: 65,536

    Dilate_35708358099161_kernel<<<blocks, DIL_THREADS>>>(in2, out4);
}